// round 4
// baseline (speedup 1.0000x reference)
#include <cuda_runtime.h>
#include <cuda_bf16.h>

// ExpmLogm on symmetric 3x3 per-voxel matrices collapses to the identity:
//   eigh(M) -> (S,U); log(exp(S)) = S; U diag(S) U^T = M  (== input).
// Optimal = D2D copy of 302 MB. R3 showed the SM copy kernel already runs at
// ~7.3 TB/s (91% of HBM spec). This round A/Bs the driver memcpy path
// (async D2D -> graph memcpy node) against the SM kernel.

#define VPT 4
#define TPB 256

// Fallback SM copy kernel (kept for safety / odd sizes).
__global__ __launch_bounds__(TPB) void expmlogm_copy_kernel(
    const float4* __restrict__ in, float4* __restrict__ out, int n4) {
    int base = blockIdx.x * (TPB * VPT) + threadIdx.x;
    float4 v[VPT];
    int idx[VPT];
    #pragma unroll
    for (int k = 0; k < VPT; k++) {
        idx[k] = base + k * TPB;
        if (idx[k] < n4) v[k] = __ldcs(&in[idx[k]]);
    }
    #pragma unroll
    for (int k = 0; k < VPT; k++) {
        if (idx[k] < n4) __stcs(&out[idx[k]], v[k]);
    }
}

extern "C" void kernel_launch(void* const* d_in, const int* in_sizes, int n_in,
                              void* d_out, int out_size) {
    const float* x = (const float*)d_in[0];
    float* out = (float*)d_out;
    int n = in_sizes[0];

    // Single async D2D memcpy — graph-capturable (memcpy node), no sync,
    // no allocation. Output dtype is float32, same as input.
    cudaError_t err = cudaMemcpyAsync(out, x, (size_t)n * sizeof(float),
                                      cudaMemcpyDeviceToDevice, 0);
    if (err != cudaSuccess) {
        // Fallback: SM copy kernel (should not trigger).
        int n4 = n / 4;
        int per_block = TPB * VPT;
        int blocks = (n4 + per_block - 1) / per_block;
        expmlogm_copy_kernel<<<blocks, TPB>>>(
            (const float4*)x, (float4*)out, n4);
    }
}